// round 17
// baseline (speedup 1.0000x reference)
#include <cuda_runtime.h>
#include <cuda_fp16.h>
#include <math.h>
#include <stdint.h>

// ---------------- problem constants ----------------
#define NB   2
#define CCH  512
#define MH   8
#define FLV  4
#define SS   13294
#define CMH  64   // C / M
#define NSM  (NB * SS * MH)   // 212704

__constant__ int cLvlW[4]   = {100, 50, 25, 13};
__constant__ int cLvlH[4]   = {100, 50, 25, 13};
__constant__ int cLvlOff[4] = {0, 10000, 12500, 13125};

// ---------------- scratch (device globals: allocation-free) ----------------
__device__ __half    g_valueH[(size_t)NB * SS * CCH]; // value fp16 [n][s][c]
__device__ __half    g_xT    [(size_t)NB * SS * CCH]; // x^T fp16 [n][s][c]
__device__ __half    g_xpT   [(size_t)NB * SS * CCH]; // (x+pos)^T fp16
__device__ __half    g_samp  [(size_t)NB * SS * CCH]; // sampled fp16 [n][s][c]
__device__ __half    g_WvH[CCH * CCH];
__device__ __half    g_WoH[CCH * CCH];
__device__ __half    g_WlwH[128 * CCH];               // [Wloc;Ww;0pad]
__device__ float     g_blw[128];
__device__ uint32_t  g_tap[(size_t)NSM * 16];  // [nsm][16]: low16 = s-offset, high16 = fp16 weight (invalid -> off 0, w 0)

// ---------------- PTX helpers (baseline sm_80+) ----------------
__device__ __forceinline__ uint32_t smem_u32(const void* p) {
    uint32_t a;
    asm("{ .reg .u64 t; cvta.to.shared.u64 t, %1; cvt.u32.u64 %0, t; }" : "=r"(a) : "l"(p));
    return a;
}
__device__ __forceinline__ void cp_async16(uint32_t dst, const void* src, uint32_t srcsize) {
    asm volatile("cp.async.cg.shared.global [%0], [%1], 16, %2;"
                 :: "r"(dst), "l"(src), "r"(srcsize) : "memory");
}
#define CP_COMMIT()  asm volatile("cp.async.commit_group;" ::: "memory")
#define CP_WAIT2()   asm volatile("cp.async.wait_group 2;" ::: "memory")

__device__ __forceinline__ void ldm_x4(uint32_t* r, uint32_t addr) {
    asm volatile("ldmatrix.sync.aligned.m8n8.x4.shared.b16 {%0,%1,%2,%3}, [%4];"
                 : "=r"(r[0]), "=r"(r[1]), "=r"(r[2]), "=r"(r[3]) : "r"(addr));
}
__device__ __forceinline__ void mma16816(float* d, const uint32_t* a, uint32_t b0, uint32_t b1) {
    asm volatile("mma.sync.aligned.m16n8k16.row.col.f32.f16.f16.f32 "
                 "{%0,%1,%2,%3}, {%4,%5,%6,%7}, {%8,%9}, {%0,%1,%2,%3};"
                 : "+f"(d[0]), "+f"(d[1]), "+f"(d[2]), "+f"(d[3])
                 : "r"(a[0]), "r"(a[1]), "r"(a[2]), "r"(a[3]), "r"(b0), "r"(b1));
}

// ---------------- fused input prep: transpose (z<NB) + weight conv (z==NB) --
__global__ void prep_inputs_kernel(
    const float* __restrict__ x, const float* __restrict__ pos,
    const float* __restrict__ Wv, const float* __restrict__ Wo,
    const float* __restrict__ Wloc, const float* __restrict__ Ww,
    const float* __restrict__ bloc, const float* __restrict__ bw)
{
    if (blockIdx.z < NB) {
        __shared__ float t[32][33];
        __shared__ float tp[32][33];
        int n = blockIdx.z, c0 = blockIdx.y * 32, s0 = blockIdx.x * 32;
        int tx = threadIdx.x & 31, ty = threadIdx.x >> 5;
        for (int r = ty; r < 32; r += 8) {
            int s = s0 + tx;
            size_t idx = ((size_t)n * CCH + c0 + r) * SS + s;
            float xv = (s < SS) ? x[idx]   : 0.f;
            float pv = (s < SS) ? pos[idx] : 0.f;
            t[r][tx]  = xv;
            tp[r][tx] = xv + pv;
        }
        __syncthreads();
        for (int r = ty; r < 32; r += 8) {
            int s = s0 + r, c = c0 + tx;
            if (s < SS) {
                size_t o = ((size_t)n * SS + s) * CCH + c;
                g_xT[o]  = __float2half_rn(t[tx][r]);
                g_xpT[o] = __float2half_rn(tp[tx][r]);
            }
        }
    } else {
        int b = blockIdx.x + gridDim.x * blockIdx.y;
        int i = b * blockDim.x + threadIdx.x;
        if (i < CCH * CCH) {
            g_WvH[i] = __float2half_rn(Wv[i]);
            g_WoH[i] = __float2half_rn(Wo[i]);
        }
        if (i < 128 * CCH) {
            int r = i >> 9, c = i & 511;
            float v = 0.f;
            if (r < 64)      v = Wloc[r * CCH + c];
            else if (r < 96) v = Ww[(r - 64) * CCH + c];
            g_WlwH[i] = __float2half_rn(v);
        }
        if (i < 128) {
            float bb = 0.f;
            if (i < 64)      bb = bloc[i];
            else if (i < 96) bb = bw[i - 64];
            g_blw[i] = bb;
        }
    }
}

// ---------------- mma.sync fp16 GEMM ----------------
// D[c,s] = sum_k A[c,k]*B[s,k]; fp16 operands, fp32 accumulate.
// Block tile 128x128, BK=32/slice, 16 slices. 6-stage swizzled smem ring,
// 2 slices per mainloop iter, ONE barrier per iter, B-fragment loads of the
// second slice hoisted into the first slice's HMMA shadow.
// outMode 0/1/2/3 as before; A2 path: y_eff==4 -> tap-prep problem (mode 3).
#define N_SLICES  16            // 512 / 32
#define STAGES    6
#define TILE_B    8192          // 128 rows * 64 bytes (unpadded, swizzled)

// swizzled byte offset for row r (0..127), 16B chunk c (0..3)
__device__ __forceinline__ uint32_t swz(int r, int c) {
    return (uint32_t)((r << 6) + (((c ^ (r >> 1)) & 3) << 4));
}

__global__ void __launch_bounds__(256, 2) gemm_fp16_mma(
    const __half* __restrict__ A, const __half* __restrict__ B,
    const float* __restrict__ bias, const float* __restrict__ scl,
    void* __restrict__ outp, int outMode, int outLd,
    const __half* __restrict__ A2, const __half* __restrict__ B2,
    const float* __restrict__ bias2,
    const float* __restrict__ vsz, const float* __restrict__ vsc)
{
    extern __shared__ char dyn[];
    const int tid = threadIdx.x, lane = tid & 31, wid = tid >> 5;
    const int warp_m = wid & 1, warp_n = wid >> 1;
    const int n = blockIdx.z;
    const int sBase = blockIdx.x * 128;
    int rowsB = SS - sBase; if (rowsB > 128) rowsB = 128;

    const __half* pA = A; const __half* pB = B;
    const float* pbias = bias;
    void* pout = outp; int ld = outLd; int mode = outMode;
    int cBase;
    if (A2 != nullptr) {
        int yEff = blockIdx.y + 4; if (yEff >= 5) yEff -= 5;   // mode-3 blocks first
        if (yEff == 4) {
            pA = A2; pB = B2; pbias = bias2; pout = nullptr; ld = 0; mode = 3; cBase = 0;
        } else {
            cBase = yEff * 128;
        }
    } else {
        cBase = blockIdx.y * 128;
    }

    const uint32_t smem = smem_u32(dyn);

    float acc[4][4][4];
#pragma unroll
    for (int i = 0; i < 4; i++)
#pragma unroll
        for (int j = 0; j < 4; j++)
#pragma unroll
            for (int e = 0; e < 4; e++) acc[i][j][e] = 0.f;

    // per-thread load coords: 512 16B-chunks per tile, 2 per thread
    const int r0 = tid >> 2, c0 = tid & 3;
    const int r1 = r0 + 64;
    const uint32_t sz0 = (r0 < rowsB) ? 16u : 0u;
    const uint32_t sz1 = (r1 < rowsB) ? 16u : 0u;
    const int rb0 = (r0 < rowsB) ? r0 : 0;
    const int rb1 = (r1 < rowsB) ? r1 : 0;
    const uint32_t dA0 = swz(r0, c0), dA1 = swz(r1, c0);

    const __half* Asrc0 = pA + (size_t)cBase * CCH;
    const __half* Bsrc0 = pB + ((size_t)n * SS + sBase) * CCH;

    auto issue = [&](int s) {
        if (s < N_SLICES) {
            int kb = s * 32;
            const __half* Asrc = Asrc0 + kb;
            const __half* Bsrc = Bsrc0 + kb;
            int st = s % STAGES;
            uint32_t sA = smem + st * TILE_B;
            uint32_t sB = smem + STAGES * TILE_B + st * TILE_B;
            cp_async16(sA + dA0, Asrc + (size_t)r0 * CCH + c0 * 8, 16u);
            cp_async16(sA + dA1, Asrc + (size_t)r1 * CCH + c0 * 8, 16u);
            cp_async16(sB + dA0, Bsrc + (size_t)rb0 * CCH + c0 * 8, sz0);
            cp_async16(sB + dA1, Bsrc + (size_t)rb1 * CCH + c0 * 8, sz1);
        }
        CP_COMMIT();
    };

    // per-lane ldmatrix addressing (swizzle-aware)
    const int aRow = warp_m * 64 + (lane & 15);
    const int aSw  = (aRow >> 1) & 3;
    const int aC   = lane >> 4;                  // 0..1
    const uint32_t aColK0 = (uint32_t)(((aC      ) ^ aSw) & 3) << 4;
    const uint32_t aColK1 = (uint32_t)(((aC ^ 2) ^ aSw) & 3) << 4;
    const uint32_t aRowOff = (uint32_t)(aRow << 6);
    const int bRow = warp_n * 32 + (lane & 7);
    const int bSw  = (bRow >> 1) & 3;
    const int bC   = lane >> 3;                  // 0..3
    const uint32_t bOff = (uint32_t)(bRow << 6) + ((uint32_t)((bC ^ bSw) & 3) << 4);

    issue(0); issue(1); issue(2); issue(3);

#pragma unroll 1
    for (int it = 0; it < N_SLICES / 2; it++) {
        CP_WAIT2();            // slices 2it, 2it+1 arrived
        __syncthreads();       // all warps done with stages from iter it-1

        const int s0 = 2 * it, s1 = 2 * it + 1;
        const uint32_t aT0 = smem + (s0 % STAGES) * TILE_B;
        const uint32_t bT0 = smem + STAGES * TILE_B + (s0 % STAGES) * TILE_B;
        const uint32_t aT1 = smem + (s1 % STAGES) * TILE_B;
        const uint32_t bT1 = smem + STAGES * TILE_B + (s1 % STAGES) * TILE_B;

        uint32_t b0[4][4], b1[4][4];
#pragma unroll
        for (int nt = 0; nt < 4; nt++)
            ldm_x4(b0[nt], bT0 + bOff + nt * 512);

        issue(s0 + 4);         // overwrites stage consumed in iter it-1 (post-barrier safe)

        // slice 0, mt 0..2
#pragma unroll
        for (int mt = 0; mt < 3; mt++) {
            uint32_t a0[4], a1[4];
            uint32_t aB = aT0 + aRowOff + mt * 1024;
            ldm_x4(a0, aB + aColK0);
            ldm_x4(a1, aB + aColK1);
#pragma unroll
            for (int nt = 0; nt < 4; nt++)
                mma16816(acc[mt][nt], a0, b0[nt][0], b0[nt][1]);
#pragma unroll
            for (int nt = 0; nt < 4; nt++)
                mma16816(acc[mt][nt], a1, b0[nt][2], b0[nt][3]);
        }

        // hoist slice-1 B fragments into slice-0's HMMA shadow
#pragma unroll
        for (int nt = 0; nt < 4; nt++)
            ldm_x4(b1[nt], bT1 + bOff + nt * 512);

        issue(s0 + 5);

        // slice 0, mt 3
        {
            uint32_t a0[4], a1[4];
            uint32_t aB = aT0 + aRowOff + 3 * 1024;
            ldm_x4(a0, aB + aColK0);
            ldm_x4(a1, aB + aColK1);
#pragma unroll
            for (int nt = 0; nt < 4; nt++)
                mma16816(acc[3][nt], a0, b0[nt][0], b0[nt][1]);
#pragma unroll
            for (int nt = 0; nt < 4; nt++)
                mma16816(acc[3][nt], a1, b0[nt][2], b0[nt][3]);
        }

        // slice 1, mt 0..3
#pragma unroll
        for (int mt = 0; mt < 4; mt++) {
            uint32_t a0[4], a1[4];
            uint32_t aB = aT1 + aRowOff + mt * 1024;
            ldm_x4(a0, aB + aColK0);
            ldm_x4(a1, aB + aColK1);
#pragma unroll
            for (int nt = 0; nt < 4; nt++)
                mma16816(acc[mt][nt], a0, b1[nt][0], b1[nt][1]);
#pragma unroll
            for (int nt = 0; nt < 4; nt++)
                mma16816(acc[mt][nt], a1, b1[nt][2], b1[nt][3]);
        }
    }
    __syncthreads();

    // ---------------- epilogue: bounce through smem ----------------
    float* smf = (float*)dyn;   // [128][132] fp32
#pragma unroll
    for (int mt = 0; mt < 4; mt++) {
#pragma unroll
        for (int nt = 0; nt < 4; nt++) {
            int m  = warp_m * 64 + mt * 16 + (lane >> 2);
            int sc = warp_n * 32 + nt * 8 + (lane & 3) * 2;
            if (mode == 1) {
                smf[(m    ) * 132 + sc    ] = acc[mt][nt][0];
                smf[(m    ) * 132 + sc + 1] = acc[mt][nt][1];
                smf[(m + 8) * 132 + sc    ] = acc[mt][nt][2];
                smf[(m + 8) * 132 + sc + 1] = acc[mt][nt][3];
            } else {
                smf[(sc    ) * 132 + m    ] = acc[mt][nt][0];
                smf[(sc + 1) * 132 + m    ] = acc[mt][nt][1];
                smf[(sc    ) * 132 + m + 8] = acc[mt][nt][2];
                smf[(sc + 1) * 132 + m + 8] = acc[mt][nt][3];
            }
        }
    }
    __syncthreads();

    if (mode == 0) {
        float* po = (float*)pout;
        for (int i = tid; i < 128 * 32; i += 256) {
            int row = i >> 5, c4 = (i & 31) * 4;
            if (row >= rowsB) continue;
            float4 v  = *(const float4*)&smf[row * 132 + c4];
            float4 bv = *(const float4*)&pbias[cBase + c4];
            v.x += bv.x; v.y += bv.y; v.z += bv.z; v.w += bv.w;
            *(float4*)&po[((size_t)n * SS + sBase + row) * ld + cBase + c4] = v;
        }
    } else if (mode == 2) {
        __half* po = (__half*)pout;
        for (int i = tid; i < 128 * 32; i += 256) {
            int row = i >> 5, c4 = (i & 31) * 4;
            if (row >= rowsB) continue;
            float4 v  = *(const float4*)&smf[row * 132 + c4];
            float4 bv = *(const float4*)&pbias[cBase + c4];
            __half2 h0 = __floats2half2_rn(v.x + bv.x, v.y + bv.y);
            __half2 h1 = __floats2half2_rn(v.z + bv.z, v.w + bv.w);
            size_t o = ((size_t)n * SS + sBase + row) * ld + cBase + c4;
            *(__half2*)(po + o)     = h0;
            *(__half2*)(po + o + 2) = h1;
        }
    } else if (mode == 3) {
        // ---- fused tap preparation from the projection tile in smem ----
        for (int k = tid; k < 128 * MH; k += 256) {
            int row = k >> 3, m = k & 7;
            if (row >= rowsB) continue;
            int s = sBase + row;
            int nsm = ((int)(n * SS) + s) * MH + m;

            int lvl = (s < 10000) ? 0 : (s < 12500) ? 1 : (s < 13125) ? 2 : 3;
            int l = s - cLvlOff[lvl];
            int Wl = cLvlW[lvl];
            int qy = l / Wl;
            int qx = l - qy * Wl;

            float scx = 2.f * vsc[(n * FLV + lvl) * 2 + 0] / vsz[(n * FLV + lvl) * 2 + 0];
            float scy = 2.f * vsc[(n * FLV + lvl) * 2 + 1] / vsz[(n * FLV + lvl) * 2 + 1];
            float gx0 = (qx + 0.5f) * scx - 1.f;
            float gy0 = (qy + 0.5f) * scy - 1.f;

            const float* rowp = &smf[row * 132];
            float offv[8];
#pragma unroll
            for (int j = 0; j < 8; j++) offv[j] = rowp[m * 8 + j] + pbias[m * 8 + j];
            float w0 = rowp[64 + m * 4 + 0] + pbias[64 + m * 4 + 0];
            float w1 = rowp[64 + m * 4 + 1] + pbias[64 + m * 4 + 1];
            float w2 = rowp[64 + m * 4 + 2] + pbias[64 + m * 4 + 2];
            float w3 = rowp[64 + m * 4 + 3] + pbias[64 + m * 4 + 3];
            float mx = fmaxf(fmaxf(w0, w1), fmaxf(w2, w3));
            float e0 = expf(w0 - mx), e1 = expf(w1 - mx), e2 = expf(w2 - mx), e3 = expf(w3 - mx);
            float inv = 1.f / (e0 + e1 + e2 + e3);
            float wt[4] = {e0 * inv, e1 * inv, e2 * inv, e3 * inv};

            uint32_t pks[16];
#pragma unroll
            for (int f = 0; f < FLV; f++) {
                float gx = offv[f * 2 + 0] * scx + gx0;
                float gy = offv[f * 2 + 1] * scy + gy0;
                int Wf = cLvlW[f], Hf = cLvlH[f];
                float xp = (gx + 1.f) * (Wf * 0.5f) - 0.5f;
                float yp = (gy + 1.f) * (Hf * 0.5f) - 0.5f;
                float x0f = floorf(xp), y0f = floorf(yp);
                int x0 = (int)x0f, y0 = (int)y0f;
                float wx1 = xp - x0f, wy1 = yp - y0f;
                float wx0 = 1.f - wx1, wy0 = 1.f - wy1;
                float wgt = wt[f];

                bool xin0 = (x0 >= 0) && (x0 < Wf);
                bool xin1 = (x0 + 1 >= 0) && (x0 + 1 < Wf);
                bool yin0 = (y0 >= 0) && (y0 < Hf);
                bool yin1 = (y0 + 1 >= 0) && (y0 + 1 < Hf);

                int   offs[4];
                float ws[4];
                bool  ok[4];
                ok[0] = yin0 && xin0; offs[0] = cLvlOff[f] + y0 * Wf + x0;           ws[0] = wgt * wx0 * wy0;
                ok[1] = yin0 && xin1; offs[1] = cLvlOff[f] + y0 * Wf + x0 + 1;       ws[1] = wgt * wx1 * wy0;
                ok[2] = yin1 && xin0; offs[2] = cLvlOff[f] + (y0 + 1) * Wf + x0;     ws[2] = wgt * wx0 * wy1;
                ok[3] = yin1 && xin1; offs[3] = cLvlOff[f] + (y0 + 1) * Wf + x0 + 1; ws[3] = wgt * wx1 * wy1;

#pragma unroll
                for (int c4 = 0; c4 < 4; c4++) {
                    uint16_t oo = ok[c4] ? (uint16_t)offs[c4] : (uint16_t)0;
                    __half   hw = ok[c4] ? __float2half_rn(ws[c4]) : __ushort_as_half((uint16_t)0);
                    pks[f * 4 + c4] = (uint32_t)oo | ((uint32_t)__half_as_ushort(hw) << 16);
                }
            }
            uint4* dst = (uint4*)(g_tap + (size_t)nsm * 16);
            dst[0] = make_uint4(pks[0],  pks[1],  pks[2],  pks[3]);
            dst[1] = make_uint4(pks[4],  pks[5],  pks[6],  pks[7]);
            dst[2] = make_uint4(pks[8],  pks[9],  pks[10], pks[11]);
            dst[3] = make_uint4(pks[12], pks[13], pks[14], pks[15]);
        }
    } else {
        // mode 1: fp32 out[n][c][SS] = (acc + bias[c]) * scl[c]
        float* po = (float*)pout;
        for (int i = tid; i < 128 * 64; i += 256) {
            int c = i >> 6, s2 = (i & 63) * 2;
            if (s2 >= rowsB) continue;
            float bv = pbias[cBase + c], sv = scl[cBase + c];
            float2 v;
            v.x = (smf[c * 132 + s2    ] + bv) * sv;
            v.y = (smf[c * 132 + s2 + 1] + bv) * sv;
            *(float2*)&po[((size_t)n * CCH + cBase + c) * SS + sBase + s2] = v;
        }
    }
}

// ---------------- lean sampler: 8 channels/lane, 4 heads/warp --------------
// block = 4 queries; head-group = 8 lanes = one (query, head); lane = 8 ch.
// fp16 (HFMA2) accumulation within groups of 4 taps; exact fp32 across groups.
__global__ void __launch_bounds__(256) sampler_kernel()
{
    int tid = threadIdx.x;
    int hg = tid >> 3;                   // 0..31 head-groups
    int lane8 = tid & 7;
    int gs = blockIdx.x * 4 + (hg >> 3); // n*SS + s
    int m  = hg & 7;
    int n  = gs / SS;
    int nsm = gs * MH + m;

    // 16 packed taps: 4 x LDG.128, broadcast within the 8-lane head-group
    const uint4* tq = (const uint4*)(g_tap + (size_t)nsm * 16);
    uint4 q[4] = {tq[0], tq[1], tq[2], tq[3]};

    const char* vb = (const char*)(g_valueH + (size_t)n * SS * CCH + m * CMH + lane8 * 8);

    float f0x = 0.f, f0y = 0.f, f1x = 0.f, f1y = 0.f;
    float f2x = 0.f, f2y = 0.f, f3x = 0.f, f3y = 0.f;

#pragma unroll
    for (int g = 0; g < 4; g++) {
        uint32_t tp0 = (&q[g].x)[0], tp1 = (&q[g].x)[1];
        uint32_t tp2 = (&q[g].x)[2], tp3 = (&q[g].x)[3];
        __half2 h0 = __floats2half2_rn(0.f, 0.f);
        __half2 h1 = h0, h2 = h0, h3 = h0;
#pragma unroll
        for (int t = 0; t < 4; t++) {
            uint32_t pk = (t == 0) ? tp0 : (t == 1) ? tp1 : (t == 2) ? tp2 : tp3;
            uint32_t off = pk & 0xFFFFu;             // invalid -> 0 with w = 0
            __half2 w2 = __half2half2(__ushort_as_half((uint16_t)(pk >> 16)));
            uint4 hv = *(const uint4*)(vb + ((size_t)off << 10));  // off * CCH * 2 bytes
            h0 = __hfma2(*(__half2*)&hv.x, w2, h0);
            h1 = __hfma2(*(__half2*)&hv.y, w2, h1);
            h2 = __hfma2(*(__half2*)&hv.z, w2, h2);
            h3 = __hfma2(*(__half2*)&hv.w, w2, h3);
        }
        float2 g0 = __half22float2(h0); f0x += g0.x; f0y += g0.y;
        float2 g1 = __half22float2(h1); f1x += g1.x; f1y += g1.y;
        float2 g2 = __half22float2(h2); f2x += g2.x; f2y += g2.y;
        float2 g3 = __half22float2(h3); f3x += g3.x; f3y += g3.y;
    }

    __half2 o0 = __floats2half2_rn(f0x, f0y);
    __half2 o1 = __floats2half2_rn(f1x, f1y);
    __half2 o2 = __floats2half2_rn(f2x, f2y);
    __half2 o3 = __floats2half2_rn(f3x, f3y);
    uint4 outv;
    outv.x = *(uint32_t*)&o0; outv.y = *(uint32_t*)&o1;
    outv.z = *(uint32_t*)&o2; outv.w = *(uint32_t*)&o3;
    *(uint4*)(g_samp + (size_t)gs * CCH + m * CMH + lane8 * 8) = outv;
}

// ---------------- launch ----------------
extern "C" void kernel_launch(void* const* d_in, const int* in_sizes, int n_in,
                              void* d_out, int out_size)
{
    const float* x    = (const float*)d_in[0];
    const float* pos  = (const float*)d_in[1];
    const float* vsz  = (const float*)d_in[3];
    const float* vsc  = (const float*)d_in[4];
    const float* Wv   = (const float*)d_in[5];
    const float* bv   = (const float*)d_in[6];
    const float* Wloc = (const float*)d_in[7];
    const float* bloc = (const float*)d_in[8];
    const float* Ww   = (const float*)d_in[9];
    const float* bw   = (const float*)d_in[10];
    const float* Wo   = (const float*)d_in[11];
    const float* bo   = (const float*)d_in[12];
    const float* scl  = (const float*)d_in[13];
    float* out = (float*)d_out;

    float *blw;
    __half *valueH, *xT, *xpT, *samp, *WvH, *WoH, *WlwH;
    cudaGetSymbolAddress((void**)&valueH, g_valueH);
    cudaGetSymbolAddress((void**)&blw,    g_blw);
    cudaGetSymbolAddress((void**)&xT,     g_xT);
    cudaGetSymbolAddress((void**)&xpT,    g_xpT);
    cudaGetSymbolAddress((void**)&samp,   g_samp);
    cudaGetSymbolAddress((void**)&WvH,    g_WvH);
    cudaGetSymbolAddress((void**)&WoH,    g_WoH);
    cudaGetSymbolAddress((void**)&WlwH,   g_WlwH);

    // dynamic smem: max(ring 12*8192 = 98304, epilogue 128*132*4 = 67584)
    const int SMEM_DYN = STAGES * 2 * TILE_B;   // 98304
    cudaFuncSetAttribute(gemm_fp16_mma, cudaFuncAttributeMaxDynamicSharedMemorySize, SMEM_DYN);

    int sTiles128 = (SS + 127) / 128;   // 104

    // fused input prep: transpose (z = 0,1) + weight conversion (z = 2)
    prep_inputs_kernel<<<dim3((SS + 31) / 32, CCH / 32, NB + 1), 256>>>(
        x, pos, Wv, Wo, Wloc, Ww, bloc, bw);

    // FUSED: value = Wv @ x + bv -> g_valueH fp16 [n][s][c]      (y_eff = 0..3, mode 2)
    //        taps  = prep(Wlw @ (x+pos) + blw) -> g_tap packed   (y_eff = 4, launched first, mode 3)
    gemm_fp16_mma<<<dim3(sTiles128, 5, NB), 256, SMEM_DYN>>>(
        WvH, xT, bv, nullptr, (void*)valueH, 2, CCH,
        WlwH, xpT, blw, vsz, vsc);

    // lean gather sampler (4 queries/block) -> g_samp [n][s][c] fp16
    sampler_kernel<<<NB * SS / 4, 256>>>();

    // out = (Wo @ sampled + bo) * scale -> d_out [n][c][s]  (mode 1)
    gemm_fp16_mma<<<dim3(sTiles128, CCH / 128, NB), 256, SMEM_DYN>>>(
        WoH, samp, bo, scl, (void*)out, 1, 0,
        nullptr, nullptr, nullptr, nullptr, nullptr);
}